// round 8
// baseline (speedup 1.0000x reference)
#include <cuda_runtime.h>
#include <cuda_fp16.h>
#include <math.h>
#include <stdint.h>

#define N_NODES 50000
#define FEAT    128
#define MAX_E   800000
#define SCAN_TILE 4096
#define SCAN_NT ((N_NODES + SCAN_TILE - 1) / SCAN_TILE)   // 13

// ---- scratch (static __device__ arrays; no runtime allocation) ----
__device__ __half g_bufT[N_NODES * FEAT];   // post-GEMM features (fp16)
__device__ float  g_bufH[N_NODES * FEAT];   // post-aggregation features (fp32)
__device__ int   g_deg[N_NODES];
__device__ float g_dis[N_NODES];
__device__ int   g_rowoff[N_NODES + 1];
__device__ int   g_cursor[N_NODES];
__device__ int2  g_csr2[MAX_E];             // (src, dis[src]) per edge
__device__ unsigned long long g_tilestate[SCAN_NT];

// ================= CSR construction =================
__global__ void k_count(const int* __restrict__ dst, int E) {
    int i = (blockIdx.x * blockDim.x + threadIdx.x) * 4;
    if (i + 3 < E) {
        int4 d = *(const int4*)&dst[i];
        atomicAdd(&g_deg[d.x], 1);
        atomicAdd(&g_deg[d.y], 1);
        atomicAdd(&g_deg[d.z], 1);
        atomicAdd(&g_deg[d.w], 1);
    } else {
        for (int j = i; j < E; j++) atomicAdd(&g_deg[dst[j]], 1);
    }
}

// decoupled-lookback scan: rowoff/cursor = exclusive scan of deg; also dis = rsqrt(deg+1)
__global__ __launch_bounds__(1024) void k_scan_dl() {
    __shared__ int sh_w[32];
    __shared__ unsigned int sh_prefix;
    int tid = threadIdx.x, lane = tid & 31, wid = tid >> 5;
    int tile = blockIdx.x;
    int i0 = tile * SCAN_TILE + tid * 4;

    int4 v = make_int4(0, 0, 0, 0);
    if (i0 < N_NODES) {
        v = *(const int4*)&g_deg[i0];
        float4 d;
        d.x = rsqrtf((float)(v.x + 1));
        d.y = rsqrtf((float)(v.y + 1));
        d.z = rsqrtf((float)(v.z + 1));
        d.w = rsqrtf((float)(v.w + 1));
        *(float4*)&g_dis[i0] = d;
    }
    int t0 = v.x, t1 = t0 + v.y, t2 = t1 + v.z, t3 = t2 + v.w;
    int sc = t3;
    #pragma unroll
    for (int d = 1; d < 32; d <<= 1) {
        int t = __shfl_up_sync(0xffffffffu, sc, d);
        if (lane >= d) sc += t;
    }
    if (lane == 31) sh_w[wid] = sc;
    __syncthreads();
    if (wid == 0) {
        int ws = sh_w[lane];
        #pragma unroll
        for (int d = 1; d < 32; d <<= 1) {
            int t = __shfl_up_sync(0xffffffffu, ws, d);
            if (lane >= d) ws += t;
        }
        sh_w[lane] = ws;
    }
    __syncthreads();
    int total = sh_w[31];
    int thr_excl = (wid ? sh_w[wid - 1] : 0) + sc - t3;

    if (tid == 0) {
        unsigned long long st = ((tile == 0) ? (2ULL << 32) : (1ULL << 32)) | (unsigned)total;
        atomicExch(&g_tilestate[tile], st);
    }
    if (wid == 0) {
        unsigned int prefix = 0;
        if (tile > 0) {
            bool have = lane < tile;
            unsigned long long s = 0;
            if (have) {
                do { s = *(volatile unsigned long long*)&g_tilestate[tile - 1 - lane]; }
                while ((unsigned)(s >> 32) == 0u);
            }
            unsigned flag = (unsigned)(s >> 32);
            unsigned mask = __ballot_sync(0xffffffffu, have && flag == 2u);
            int firstInc = __ffs(mask) - 1;   // exists: tile 0 is always INCLUSIVE
            unsigned contrib = (have && lane <= firstInc) ? (unsigned)s : 0u;
            #pragma unroll
            for (int d = 16; d; d >>= 1) contrib += __shfl_xor_sync(0xffffffffu, contrib, d);
            prefix = contrib;
            if (lane == 0)
                atomicExch(&g_tilestate[tile], (2ULL << 32) | (unsigned)(prefix + (unsigned)total));
        }
        if (lane == 0) sh_prefix = prefix;
    }
    __syncthreads();
    int base = (int)sh_prefix + thr_excl;
    if (i0 < N_NODES) {
        int4 o = make_int4(base, base + t0, base + t1, base + t2);
        *(int4*)&g_rowoff[i0] = o;
        *(int4*)&g_cursor[i0] = o;
    }
    if (tile == SCAN_NT - 1 && tid == 0) g_rowoff[N_NODES] = (int)sh_prefix + total;
}

// fill packed CSR: entry = (src, dis[src])
__global__ void k_fill(const int* __restrict__ src, const int* __restrict__ dst, int E) {
    int i = (blockIdx.x * blockDim.x + threadIdx.x) * 4;
    if (i + 3 < E) {
        int4 s = *(const int4*)&src[i];
        int4 d = *(const int4*)&dst[i];
        float f0 = g_dis[s.x], f1 = g_dis[s.y], f2 = g_dis[s.z], f3 = g_dis[s.w];
        int p0 = atomicAdd(&g_cursor[d.x], 1);
        int p1 = atomicAdd(&g_cursor[d.y], 1);
        int p2 = atomicAdd(&g_cursor[d.z], 1);
        int p3 = atomicAdd(&g_cursor[d.w], 1);
        g_csr2[p0] = make_int2(s.x, __float_as_int(f0));
        g_csr2[p1] = make_int2(s.y, __float_as_int(f1));
        g_csr2[p2] = make_int2(s.z, __float_as_int(f2));
        g_csr2[p3] = make_int2(s.w, __float_as_int(f3));
    } else {
        for (int j = i; j < E; j++) {
            int sj = src[j];
            int p = atomicAdd(&g_cursor[dst[j]], 1);
            g_csr2[p] = make_int2(sj, __float_as_int(g_dis[sj]));
        }
    }
}

// ================= fp16 2-pass split GEMM via warp mma.sync =============
// C[nrows,128] = A[nrows,128] @ W[128,128]:  D = Ahi*W16 + Alo*W16
// A split fp16 hi/lo (error ~2^-22), W rounded to fp16 once (error ~2^-12).
// Tile: 64 rows x 128 cols per block; 8 warps, each 16 rows x 64 cols
// (warp = rowgrp*2 + colhalf). 32 acc regs/thread, 3 CTAs/SM.
#define WROW 72

__device__ __forceinline__ uint32_t pack_h2(__half a, __half b) {
    __half2 h = __halves2half2(a, b);
    return *(uint32_t*)&h;
}
__device__ __forceinline__ void split2h(float x, float y, uint32_t& hi, uint32_t& lo) {
    __half h0 = __float2half_rn(x), h1 = __float2half_rn(y);
    __half l0 = __float2half_rn(x - __half2float(h0));
    __half l1 = __float2half_rn(y - __half2float(h1));
    hi = pack_h2(h0, h1);
    lo = pack_h2(l0, l1);
}
__device__ __forceinline__ void mma_f16(float* c, const uint32_t* a, uint32_t b0, uint32_t b1) {
    asm volatile(
        "mma.sync.aligned.m16n8k16.row.col.f32.f16.f16.f32 "
        "{%0,%1,%2,%3}, {%4,%5,%6,%7}, {%8,%9}, {%0,%1,%2,%3};"
        : "+f"(c[0]), "+f"(c[1]), "+f"(c[2]), "+f"(c[3])
        : "r"(a[0]), "r"(a[1]), "r"(a[2]), "r"(a[3]), "r"(b0), "r"(b1));
}

__global__ __launch_bounds__(256, 3) void k_gemm_mma(const float* __restrict__ A,
                                                     const float* __restrict__ W,
                                                     __half* __restrict__ C, int nrows) {
    __shared__ uint32_t Wh[128 * WROW];

    int tid = threadIdx.x, wid = tid >> 5, lane = tid & 31;
    int g = lane >> 2, t = lane & 3;
    int rowgrp = wid >> 1, colhalf = wid & 1;

    // stage W as fp16 pairs, fragment-major
    for (int idx = tid; idx < 64 * 128; idx += 256) {
        int p = idx >> 7, n = idx & 127;
        int k = p * 2;
        float w0 = W[k * FEAT + n];
        float w1 = W[(k + 1) * FEAT + n];
        int kstep = p >> 3, q = p & 7;
        int word = n * WROW + kstep * 8 + (q & 3) * 2 + (q >> 2);
        Wh[word] = pack_h2(__float2half_rn(w0), __float2half_rn(w1));
    }
    __syncthreads();

    int r0 = blockIdx.x * 64 + rowgrp * 16 + g;
    int r1 = r0 + 8;
    bool v0 = r0 < nrows, v1 = r1 < nrows;

    float acc[8][4];
    #pragma unroll
    for (int j = 0; j < 8; j++)
        #pragma unroll
        for (int c = 0; c < 4; c++) acc[j][c] = 0.0f;

    const int bbase = colhalf * 8 * 8 * WROW + g * WROW;   // n0 = colhalf*8 + j

    #pragma unroll
    for (int kstep = 0; kstep < 8; kstep++) {
        int ka = kstep * 16 + 2 * t;
        float2 z = make_float2(0.f, 0.f);
        float2 p00 = v0 ? *(const float2*)&A[r0 * FEAT + ka]     : z;
        float2 p01 = v0 ? *(const float2*)&A[r0 * FEAT + ka + 8] : z;
        float2 p10 = v1 ? *(const float2*)&A[r1 * FEAT + ka]     : z;
        float2 p11 = v1 ? *(const float2*)&A[r1 * FEAT + ka + 8] : z;
        uint32_t ahi[4], alo[4];
        split2h(p00.x, p00.y, ahi[0], alo[0]);
        split2h(p10.x, p10.y, ahi[1], alo[1]);
        split2h(p01.x, p01.y, ahi[2], alo[2]);
        split2h(p11.x, p11.y, ahi[3], alo[3]);

        int bk = kstep * 8 + t * 2;
        #pragma unroll
        for (int j = 0; j < 8; j++) {
            uint2 bh = *(const uint2*)&Wh[bbase + j * 8 * WROW + bk];
            mma_f16(acc[j], ahi, bh.x, bh.y);
            mma_f16(acc[j], alo, bh.x, bh.y);
        }
    }

    #pragma unroll
    for (int j = 0; j < 8; j++) {
        int col = (colhalf * 8 + j) * 8 + 2 * t;
        if (v0) *(__half2*)&C[r0 * FEAT + col] = __floats2half2_rn(acc[j][0], acc[j][1]);
        if (v1) *(__half2*)&C[r1 * FEAT + col] = __floats2half2_rn(acc[j][2], acc[j][3]);
    }
}

// ================= aggregation (one warp per dst node, packed CSR) =======
__device__ __forceinline__ float elu1(float v) { return v > 0.0f ? v : expm1f(v); }

__device__ __forceinline__ float4 ld_row_h(const __half* __restrict__ T, int s, int lane) {
    uint2 u = *(const uint2*)(T + s * FEAT + lane * 4);
    __half2 h0 = *(__half2*)&u.x;
    __half2 h1 = *(__half2*)&u.y;
    float2 f0 = __half22float2(h0);
    float2 f1 = __half22float2(h1);
    return make_float4(f0.x, f0.y, f1.x, f1.y);
}

// FUSE_FINAL=0: Hout = ELU(acc+bias). FUSE_FINAL=1: out = ELU(acc+bias)@Wl + bl.
template<int FUSE_FINAL>
__global__ __launch_bounds__(256) void k_agg_t(const __half* __restrict__ T,
                                               const float* __restrict__ bias,
                                               float* __restrict__ Hout,
                                               const float* __restrict__ Wl,
                                               const float* __restrict__ bl,
                                               float* __restrict__ out) {
    int warp = (int)((blockIdx.x * blockDim.x + threadIdx.x) >> 5);
    int lane = threadIdx.x & 31;
    if (warp >= N_NODES) return;
    int node = warp;
    float dd = g_dis[node];

    float4 acc = ld_row_h(T, node, lane);
    float ws = dd * dd;                        // self-loop weight
    acc.x *= ws; acc.y *= ws; acc.z *= ws; acc.w *= ws;

    int beg = g_rowoff[node];
    int end = g_rowoff[node + 1];
    int e = beg;
    for (; e + 3 < end; e += 4) {
        int2 p0 = g_csr2[e],     p1 = g_csr2[e + 1];
        int2 p2 = g_csr2[e + 2], p3 = g_csr2[e + 3];
        float w0 = __int_as_float(p0.y) * dd, w1 = __int_as_float(p1.y) * dd;
        float w2 = __int_as_float(p2.y) * dd, w3 = __int_as_float(p3.y) * dd;
        float4 v0 = ld_row_h(T, p0.x, lane);
        float4 v1 = ld_row_h(T, p1.x, lane);
        float4 v2 = ld_row_h(T, p2.x, lane);
        float4 v3 = ld_row_h(T, p3.x, lane);
        acc.x = fmaf(w0, v0.x, fmaf(w1, v1.x, fmaf(w2, v2.x, fmaf(w3, v3.x, acc.x))));
        acc.y = fmaf(w0, v0.y, fmaf(w1, v1.y, fmaf(w2, v2.y, fmaf(w3, v3.y, acc.y))));
        acc.z = fmaf(w0, v0.z, fmaf(w1, v1.z, fmaf(w2, v2.z, fmaf(w3, v3.z, acc.z))));
        acc.w = fmaf(w0, v0.w, fmaf(w1, v1.w, fmaf(w2, v2.w, fmaf(w3, v3.w, acc.w))));
    }
    for (; e < end; e++) {
        int2 p0 = g_csr2[e];
        float w0 = __int_as_float(p0.y) * dd;
        float4 v0 = ld_row_h(T, p0.x, lane);
        acc.x = fmaf(w0, v0.x, acc.x);
        acc.y = fmaf(w0, v0.y, acc.y);
        acc.z = fmaf(w0, v0.z, acc.z);
        acc.w = fmaf(w0, v0.w, acc.w);
    }

    float4 b = *(const float4*)&bias[lane * 4];
    float4 r;
    r.x = elu1(acc.x + b.x);
    r.y = elu1(acc.y + b.y);
    r.z = elu1(acc.z + b.z);
    r.w = elu1(acc.w + b.w);

    if (FUSE_FINAL) {
        float4 w = *(const float4*)&Wl[lane * 4];
        float s = r.x * w.x + r.y * w.y + r.z * w.z + r.w * w.w;
        #pragma unroll
        for (int d = 16; d; d >>= 1) s += __shfl_xor_sync(0xffffffffu, s, d);
        if (lane == 0) out[node] = s + bl[0];
    } else {
        *(float4*)&Hout[node * FEAT + lane * 4] = r;
    }
}

// ================= launch =================
extern "C" void kernel_launch(void* const* d_in, const int* in_sizes, int n_in,
                              void* d_out, int out_size) {
    const float* x  = (const float*)d_in[0];
    const float* Ws = (const float*)d_in[1];
    const float* bs = (const float*)d_in[2];
    const float* Wl = (const float*)d_in[3];
    const float* bl = (const float*)d_in[4];
    const int*   ei = (const int*)d_in[5];
    const int E = in_sizes[5] / 2;
    const int* src = ei;
    const int* dst = ei + E;
    float* out = (float*)d_out;

    float* hbuf = nullptr;
    __half* tbuf = nullptr;
    void *degp = nullptr, *tsp = nullptr;
    cudaGetSymbolAddress((void**)&hbuf, g_bufH);
    cudaGetSymbolAddress((void**)&tbuf, g_bufT);
    cudaGetSymbolAddress(&degp, g_deg);
    cudaGetSymbolAddress(&tsp, g_tilestate);

    // graph structure
    cudaMemsetAsync(degp, 0, N_NODES * sizeof(int), 0);
    cudaMemsetAsync(tsp, 0, SCAN_NT * sizeof(unsigned long long), 0);
    k_count<<<(E / 4 + 255) / 256, 256>>>(dst, E);
    k_scan_dl<<<SCAN_NT, 1024>>>();
    k_fill<<<(E / 4 + 255) / 256, 256>>>(src, dst, E);

    const int ntiles = (N_NODES + 63) / 64;   // 782
    const int nagg   = (N_NODES + 7) / 8;
    for (int i = 0; i < 3; i++) {
        const float* Ain = (i == 0) ? x : hbuf;
        k_gemm_mma<<<ntiles, 256>>>(Ain, Ws + i * FEAT * FEAT, tbuf, N_NODES);
        if (i < 2)
            k_agg_t<0><<<nagg, 256>>>(tbuf, bs + i * FEAT, hbuf, nullptr, nullptr, nullptr);
        else
            k_agg_t<1><<<nagg, 256>>>(tbuf, bs + i * FEAT, nullptr, Wl, bl, out);
    }
}

// round 9
// speedup vs baseline: 1.0269x; 1.0269x over previous
#include <cuda_runtime.h>
#include <cuda_fp16.h>
#include <math.h>
#include <stdint.h>

#define N_NODES 50000
#define FEAT    128
#define MAX_E   800000
#define SCAN_TILE 4096
#define SCAN_NT ((N_NODES + SCAN_TILE - 1) / SCAN_TILE)   // 13

// ---- scratch (static __device__ arrays; no runtime allocation) ----
__device__ __half g_bufT[N_NODES * FEAT];   // post-GEMM features (fp16)
__device__ float  g_bufH[N_NODES * FEAT];   // post-aggregation features (fp32)
__device__ int   g_deg[N_NODES];
__device__ float g_dis[N_NODES];
__device__ int   g_rowoff[N_NODES + 1];
__device__ int   g_cursor[N_NODES];
__device__ int2  g_csr2[MAX_E];             // (src, dis[src]) per edge
__device__ unsigned long long g_tilestate[SCAN_NT];

// ================= CSR construction =================
__global__ void k_count(const int* __restrict__ dst, int E) {
    int i = (blockIdx.x * blockDim.x + threadIdx.x) * 4;
    if (i + 3 < E) {
        int4 d = *(const int4*)&dst[i];
        atomicAdd(&g_deg[d.x], 1);
        atomicAdd(&g_deg[d.y], 1);
        atomicAdd(&g_deg[d.z], 1);
        atomicAdd(&g_deg[d.w], 1);
    } else {
        for (int j = i; j < E; j++) atomicAdd(&g_deg[dst[j]], 1);
    }
}

// decoupled-lookback scan: rowoff/cursor = exclusive scan of deg; also dis = rsqrt(deg+1)
__global__ __launch_bounds__(1024) void k_scan_dl() {
    __shared__ int sh_w[32];
    __shared__ unsigned int sh_prefix;
    int tid = threadIdx.x, lane = tid & 31, wid = tid >> 5;
    int tile = blockIdx.x;
    int i0 = tile * SCAN_TILE + tid * 4;

    int4 v = make_int4(0, 0, 0, 0);
    if (i0 < N_NODES) {
        v = *(const int4*)&g_deg[i0];
        float4 d;
        d.x = rsqrtf((float)(v.x + 1));
        d.y = rsqrtf((float)(v.y + 1));
        d.z = rsqrtf((float)(v.z + 1));
        d.w = rsqrtf((float)(v.w + 1));
        *(float4*)&g_dis[i0] = d;
    }
    int t0 = v.x, t1 = t0 + v.y, t2 = t1 + v.z, t3 = t2 + v.w;
    int sc = t3;
    #pragma unroll
    for (int d = 1; d < 32; d <<= 1) {
        int t = __shfl_up_sync(0xffffffffu, sc, d);
        if (lane >= d) sc += t;
    }
    if (lane == 31) sh_w[wid] = sc;
    __syncthreads();
    if (wid == 0) {
        int ws = sh_w[lane];
        #pragma unroll
        for (int d = 1; d < 32; d <<= 1) {
            int t = __shfl_up_sync(0xffffffffu, ws, d);
            if (lane >= d) ws += t;
        }
        sh_w[lane] = ws;
    }
    __syncthreads();
    int total = sh_w[31];
    int thr_excl = (wid ? sh_w[wid - 1] : 0) + sc - t3;

    if (tid == 0) {
        unsigned long long st = ((tile == 0) ? (2ULL << 32) : (1ULL << 32)) | (unsigned)total;
        atomicExch(&g_tilestate[tile], st);
    }
    if (wid == 0) {
        unsigned int prefix = 0;
        if (tile > 0) {
            bool have = lane < tile;
            unsigned long long s = 0;
            if (have) {
                do { s = *(volatile unsigned long long*)&g_tilestate[tile - 1 - lane]; }
                while ((unsigned)(s >> 32) == 0u);
            }
            unsigned flag = (unsigned)(s >> 32);
            unsigned mask = __ballot_sync(0xffffffffu, have && flag == 2u);
            int firstInc = __ffs(mask) - 1;   // exists: tile 0 is always INCLUSIVE
            unsigned contrib = (have && lane <= firstInc) ? (unsigned)s : 0u;
            #pragma unroll
            for (int d = 16; d; d >>= 1) contrib += __shfl_xor_sync(0xffffffffu, contrib, d);
            prefix = contrib;
            if (lane == 0)
                atomicExch(&g_tilestate[tile], (2ULL << 32) | (unsigned)(prefix + (unsigned)total));
        }
        if (lane == 0) sh_prefix = prefix;
    }
    __syncthreads();
    int base = (int)sh_prefix + thr_excl;
    if (i0 < N_NODES) {
        int4 o = make_int4(base, base + t0, base + t1, base + t2);
        *(int4*)&g_rowoff[i0] = o;
        *(int4*)&g_cursor[i0] = o;
    }
    if (tile == SCAN_NT - 1 && tid == 0) g_rowoff[N_NODES] = (int)sh_prefix + total;
}

// fill packed CSR: entry = (src, dis[src])
__global__ void k_fill(const int* __restrict__ src, const int* __restrict__ dst, int E) {
    int i = (blockIdx.x * blockDim.x + threadIdx.x) * 4;
    if (i + 3 < E) {
        int4 s = *(const int4*)&src[i];
        int4 d = *(const int4*)&dst[i];
        float f0 = g_dis[s.x], f1 = g_dis[s.y], f2 = g_dis[s.z], f3 = g_dis[s.w];
        int p0 = atomicAdd(&g_cursor[d.x], 1);
        int p1 = atomicAdd(&g_cursor[d.y], 1);
        int p2 = atomicAdd(&g_cursor[d.z], 1);
        int p3 = atomicAdd(&g_cursor[d.w], 1);
        g_csr2[p0] = make_int2(s.x, __float_as_int(f0));
        g_csr2[p1] = make_int2(s.y, __float_as_int(f1));
        g_csr2[p2] = make_int2(s.z, __float_as_int(f2));
        g_csr2[p3] = make_int2(s.w, __float_as_int(f3));
    } else {
        for (int j = i; j < E; j++) {
            int sj = src[j];
            int p = atomicAdd(&g_cursor[dst[j]], 1);
            g_csr2[p] = make_int2(sj, __float_as_int(g_dis[sj]));
        }
    }
}

// ================= fp16 2-pass split GEMM via warp mma.sync =============
// C[nrows,128] = A[nrows,128] @ W[128,128]:  D = Ahi*W16 + Alo*W16
// A split fp16 hi/lo (error ~2^-22), W rounded to fp16 once (error ~2^-12).
// Tile: 128 rows x 128 cols per block (good W-staging amortization);
// 512 threads / 16 warps, each warp 16 rows x 64 cols (32 acc regs) ->
// 2 CTAs/SM = 32 warps resident for latency hiding.
#define WROW 72

__device__ __forceinline__ uint32_t pack_h2(__half a, __half b) {
    __half2 h = __halves2half2(a, b);
    return *(uint32_t*)&h;
}
__device__ __forceinline__ void split2h(float x, float y, uint32_t& hi, uint32_t& lo) {
    __half h0 = __float2half_rn(x), h1 = __float2half_rn(y);
    __half l0 = __float2half_rn(x - __half2float(h0));
    __half l1 = __float2half_rn(y - __half2float(h1));
    hi = pack_h2(h0, h1);
    lo = pack_h2(l0, l1);
}
__device__ __forceinline__ void mma_f16(float* c, const uint32_t* a, uint32_t b0, uint32_t b1) {
    asm volatile(
        "mma.sync.aligned.m16n8k16.row.col.f32.f16.f16.f32 "
        "{%0,%1,%2,%3}, {%4,%5,%6,%7}, {%8,%9}, {%0,%1,%2,%3};"
        : "+f"(c[0]), "+f"(c[1]), "+f"(c[2]), "+f"(c[3])
        : "r"(a[0]), "r"(a[1]), "r"(a[2]), "r"(a[3]), "r"(b0), "r"(b1));
}

__global__ __launch_bounds__(512, 2) void k_gemm_mma(const float* __restrict__ A,
                                                     const float* __restrict__ W,
                                                     __half* __restrict__ C, int nrows) {
    __shared__ uint32_t Wh[128 * WROW];

    int tid = threadIdx.x, wid = tid >> 5, lane = tid & 31;
    int g = lane >> 2, t = lane & 3;
    int rowgrp = wid >> 1, colhalf = wid & 1;

    // stage W as fp16 pairs, fragment-major (512 threads, 16 iters)
    for (int idx = tid; idx < 64 * 128; idx += 512) {
        int p = idx >> 7, n = idx & 127;
        int k = p * 2;
        float w0 = W[k * FEAT + n];
        float w1 = W[(k + 1) * FEAT + n];
        int kstep = p >> 3, q = p & 7;
        int word = n * WROW + kstep * 8 + (q & 3) * 2 + (q >> 2);
        Wh[word] = pack_h2(__float2half_rn(w0), __float2half_rn(w1));
    }
    __syncthreads();

    int r0 = blockIdx.x * 128 + rowgrp * 16 + g;
    int r1 = r0 + 8;
    bool v0 = r0 < nrows, v1 = r1 < nrows;

    float acc[8][4];
    #pragma unroll
    for (int j = 0; j < 8; j++)
        #pragma unroll
        for (int c = 0; c < 4; c++) acc[j][c] = 0.0f;

    const int bbase = colhalf * 8 * 8 * WROW + g * WROW;   // n0 = colhalf*8 + j

    #pragma unroll
    for (int kstep = 0; kstep < 8; kstep++) {
        int ka = kstep * 16 + 2 * t;
        float2 z = make_float2(0.f, 0.f);
        float2 p00 = v0 ? *(const float2*)&A[r0 * FEAT + ka]     : z;
        float2 p01 = v0 ? *(const float2*)&A[r0 * FEAT + ka + 8] : z;
        float2 p10 = v1 ? *(const float2*)&A[r1 * FEAT + ka]     : z;
        float2 p11 = v1 ? *(const float2*)&A[r1 * FEAT + ka + 8] : z;
        uint32_t ahi[4], alo[4];
        split2h(p00.x, p00.y, ahi[0], alo[0]);
        split2h(p10.x, p10.y, ahi[1], alo[1]);
        split2h(p01.x, p01.y, ahi[2], alo[2]);
        split2h(p11.x, p11.y, ahi[3], alo[3]);

        int bk = kstep * 8 + t * 2;
        #pragma unroll
        for (int j = 0; j < 8; j++) {
            uint2 bh = *(const uint2*)&Wh[bbase + j * 8 * WROW + bk];
            mma_f16(acc[j], ahi, bh.x, bh.y);
            mma_f16(acc[j], alo, bh.x, bh.y);
        }
    }

    #pragma unroll
    for (int j = 0; j < 8; j++) {
        int col = (colhalf * 8 + j) * 8 + 2 * t;
        if (v0) *(__half2*)&C[r0 * FEAT + col] = __floats2half2_rn(acc[j][0], acc[j][1]);
        if (v1) *(__half2*)&C[r1 * FEAT + col] = __floats2half2_rn(acc[j][2], acc[j][3]);
    }
}

// ================= aggregation (one warp per dst node, packed CSR) =======
__device__ __forceinline__ float elu1(float v) { return v > 0.0f ? v : expm1f(v); }

__device__ __forceinline__ float4 ld_row_h(const __half* __restrict__ T, int s, int lane) {
    uint2 u = *(const uint2*)(T + s * FEAT + lane * 4);
    __half2 h0 = *(__half2*)&u.x;
    __half2 h1 = *(__half2*)&u.y;
    float2 f0 = __half22float2(h0);
    float2 f1 = __half22float2(h1);
    return make_float4(f0.x, f0.y, f1.x, f1.y);
}

// FUSE_FINAL=0: Hout = ELU(acc+bias). FUSE_FINAL=1: out = ELU(acc+bias)@Wl + bl.
template<int FUSE_FINAL>
__global__ __launch_bounds__(256) void k_agg_t(const __half* __restrict__ T,
                                               const float* __restrict__ bias,
                                               float* __restrict__ Hout,
                                               const float* __restrict__ Wl,
                                               const float* __restrict__ bl,
                                               float* __restrict__ out) {
    int warp = (int)((blockIdx.x * blockDim.x + threadIdx.x) >> 5);
    int lane = threadIdx.x & 31;
    if (warp >= N_NODES) return;
    int node = warp;
    float dd = g_dis[node];

    float4 acc = ld_row_h(T, node, lane);
    float ws = dd * dd;                        // self-loop weight
    acc.x *= ws; acc.y *= ws; acc.z *= ws; acc.w *= ws;

    int beg = g_rowoff[node];
    int end = g_rowoff[node + 1];
    int e = beg;
    for (; e + 3 < end; e += 4) {
        int2 p0 = g_csr2[e],     p1 = g_csr2[e + 1];
        int2 p2 = g_csr2[e + 2], p3 = g_csr2[e + 3];
        float w0 = __int_as_float(p0.y) * dd, w1 = __int_as_float(p1.y) * dd;
        float w2 = __int_as_float(p2.y) * dd, w3 = __int_as_float(p3.y) * dd;
        float4 v0 = ld_row_h(T, p0.x, lane);
        float4 v1 = ld_row_h(T, p1.x, lane);
        float4 v2 = ld_row_h(T, p2.x, lane);
        float4 v3 = ld_row_h(T, p3.x, lane);
        acc.x = fmaf(w0, v0.x, fmaf(w1, v1.x, fmaf(w2, v2.x, fmaf(w3, v3.x, acc.x))));
        acc.y = fmaf(w0, v0.y, fmaf(w1, v1.y, fmaf(w2, v2.y, fmaf(w3, v3.y, acc.y))));
        acc.z = fmaf(w0, v0.z, fmaf(w1, v1.z, fmaf(w2, v2.z, fmaf(w3, v3.z, acc.z))));
        acc.w = fmaf(w0, v0.w, fmaf(w1, v1.w, fmaf(w2, v2.w, fmaf(w3, v3.w, acc.w))));
    }
    for (; e < end; e++) {
        int2 p0 = g_csr2[e];
        float w0 = __int_as_float(p0.y) * dd;
        float4 v0 = ld_row_h(T, p0.x, lane);
        acc.x = fmaf(w0, v0.x, acc.x);
        acc.y = fmaf(w0, v0.y, acc.y);
        acc.z = fmaf(w0, v0.z, acc.z);
        acc.w = fmaf(w0, v0.w, acc.w);
    }

    float4 b = *(const float4*)&bias[lane * 4];
    float4 r;
    r.x = elu1(acc.x + b.x);
    r.y = elu1(acc.y + b.y);
    r.z = elu1(acc.z + b.z);
    r.w = elu1(acc.w + b.w);

    if (FUSE_FINAL) {
        float4 w = *(const float4*)&Wl[lane * 4];
        float s = r.x * w.x + r.y * w.y + r.z * w.z + r.w * w.w;
        #pragma unroll
        for (int d = 16; d; d >>= 1) s += __shfl_xor_sync(0xffffffffu, s, d);
        if (lane == 0) out[node] = s + bl[0];
    } else {
        *(float4*)&Hout[node * FEAT + lane * 4] = r;
    }
}

// ================= launch =================
extern "C" void kernel_launch(void* const* d_in, const int* in_sizes, int n_in,
                              void* d_out, int out_size) {
    const float* x  = (const float*)d_in[0];
    const float* Ws = (const float*)d_in[1];
    const float* bs = (const float*)d_in[2];
    const float* Wl = (const float*)d_in[3];
    const float* bl = (const float*)d_in[4];
    const int*   ei = (const int*)d_in[5];
    const int E = in_sizes[5] / 2;
    const int* src = ei;
    const int* dst = ei + E;
    float* out = (float*)d_out;

    float* hbuf = nullptr;
    __half* tbuf = nullptr;
    void *degp = nullptr, *tsp = nullptr;
    cudaGetSymbolAddress((void**)&hbuf, g_bufH);
    cudaGetSymbolAddress((void**)&tbuf, g_bufT);
    cudaGetSymbolAddress(&degp, g_deg);
    cudaGetSymbolAddress(&tsp, g_tilestate);

    // graph structure
    cudaMemsetAsync(degp, 0, N_NODES * sizeof(int), 0);
    cudaMemsetAsync(tsp, 0, SCAN_NT * sizeof(unsigned long long), 0);
    k_count<<<(E / 4 + 255) / 256, 256>>>(dst, E);
    k_scan_dl<<<SCAN_NT, 1024>>>();
    k_fill<<<(E / 4 + 255) / 256, 256>>>(src, dst, E);

    const int ntiles = (N_NODES + 127) / 128;   // 391
    const int nagg   = (N_NODES + 7) / 8;
    for (int i = 0; i < 3; i++) {
        const float* Ain = (i == 0) ? x : hbuf;
        k_gemm_mma<<<ntiles, 512>>>(Ain, Ws + i * FEAT * FEAT, tbuf, N_NODES);
        if (i < 2)
            k_agg_t<0><<<nagg, 256>>>(tbuf, bs + i * FEAT, hbuf, nullptr, nullptr, nullptr);
        else
            k_agg_t<1><<<nagg, 256>>>(tbuf, bs + i * FEAT, nullptr, Wl, bl, out);
    }
}

// round 10
// speedup vs baseline: 1.0345x; 1.0074x over previous
#include <cuda_runtime.h>
#include <cuda_fp16.h>
#include <math.h>
#include <stdint.h>

#define N_NODES 50000
#define FEAT    128
#define MAX_E   800000
#define SCAN_TILE 4096
#define SCAN_NT ((N_NODES + SCAN_TILE - 1) / SCAN_TILE)   // 13

// ---- scratch (static __device__ arrays; no runtime allocation) ----
__device__ __half g_bufT[N_NODES * FEAT];   // post-GEMM features (fp16)
__device__ float  g_bufH[N_NODES * FEAT];   // post-aggregation features (fp32)
__device__ int   g_deg[N_NODES];
__device__ float g_dis[N_NODES];
__device__ int   g_rowoff[N_NODES + 1];
__device__ int   g_rank[MAX_E];             // per-edge rank within its dst list
__device__ int2  g_csr2[MAX_E];             // (src, dis[src]) per edge
__device__ unsigned long long g_tilestate[SCAN_NT];

// ================= CSR construction =================
// pass 1: count in-degree AND record each edge's rank within its dst bucket
__global__ void k_count(const int* __restrict__ dst, int E) {
    int i = (blockIdx.x * blockDim.x + threadIdx.x) * 4;
    if (i + 3 < E) {
        int4 d = *(const int4*)&dst[i];
        int4 r;
        r.x = atomicAdd(&g_deg[d.x], 1);
        r.y = atomicAdd(&g_deg[d.y], 1);
        r.z = atomicAdd(&g_deg[d.z], 1);
        r.w = atomicAdd(&g_deg[d.w], 1);
        *(int4*)&g_rank[i] = r;
    } else {
        for (int j = i; j < E; j++) g_rank[j] = atomicAdd(&g_deg[dst[j]], 1);
    }
}

// decoupled-lookback scan: rowoff = exclusive scan of deg; also dis = rsqrt(deg+1)
__global__ __launch_bounds__(1024) void k_scan_dl() {
    __shared__ int sh_w[32];
    __shared__ unsigned int sh_prefix;
    int tid = threadIdx.x, lane = tid & 31, wid = tid >> 5;
    int tile = blockIdx.x;
    int i0 = tile * SCAN_TILE + tid * 4;

    int4 v = make_int4(0, 0, 0, 0);
    if (i0 < N_NODES) {
        v = *(const int4*)&g_deg[i0];
        float4 d;
        d.x = rsqrtf((float)(v.x + 1));
        d.y = rsqrtf((float)(v.y + 1));
        d.z = rsqrtf((float)(v.z + 1));
        d.w = rsqrtf((float)(v.w + 1));
        *(float4*)&g_dis[i0] = d;
    }
    int t0 = v.x, t1 = t0 + v.y, t2 = t1 + v.z, t3 = t2 + v.w;
    int sc = t3;
    #pragma unroll
    for (int d = 1; d < 32; d <<= 1) {
        int t = __shfl_up_sync(0xffffffffu, sc, d);
        if (lane >= d) sc += t;
    }
    if (lane == 31) sh_w[wid] = sc;
    __syncthreads();
    if (wid == 0) {
        int ws = sh_w[lane];
        #pragma unroll
        for (int d = 1; d < 32; d <<= 1) {
            int t = __shfl_up_sync(0xffffffffu, ws, d);
            if (lane >= d) ws += t;
        }
        sh_w[lane] = ws;
    }
    __syncthreads();
    int total = sh_w[31];
    int thr_excl = (wid ? sh_w[wid - 1] : 0) + sc - t3;

    if (tid == 0) {
        unsigned long long st = ((tile == 0) ? (2ULL << 32) : (1ULL << 32)) | (unsigned)total;
        atomicExch(&g_tilestate[tile], st);
    }
    if (wid == 0) {
        unsigned int prefix = 0;
        if (tile > 0) {
            bool have = lane < tile;
            unsigned long long s = 0;
            if (have) {
                do { s = *(volatile unsigned long long*)&g_tilestate[tile - 1 - lane]; }
                while ((unsigned)(s >> 32) == 0u);
            }
            unsigned flag = (unsigned)(s >> 32);
            unsigned mask = __ballot_sync(0xffffffffu, have && flag == 2u);
            int firstInc = __ffs(mask) - 1;   // exists: tile 0 is always INCLUSIVE
            unsigned contrib = (have && lane <= firstInc) ? (unsigned)s : 0u;
            #pragma unroll
            for (int d = 16; d; d >>= 1) contrib += __shfl_xor_sync(0xffffffffu, contrib, d);
            prefix = contrib;
            if (lane == 0)
                atomicExch(&g_tilestate[tile], (2ULL << 32) | (unsigned)(prefix + (unsigned)total));
        }
        if (lane == 0) sh_prefix = prefix;
    }
    __syncthreads();
    int base = (int)sh_prefix + thr_excl;
    if (i0 < N_NODES) {
        int4 o = make_int4(base, base + t0, base + t1, base + t2);
        *(int4*)&g_rowoff[i0] = o;
    }
    if (tile == SCAN_NT - 1 && tid == 0) g_rowoff[N_NODES] = (int)sh_prefix + total;
}

// pass 2 (no atomics): scatter (src, dis[src]) to rowoff[dst] + rank
__global__ void k_fill(const int* __restrict__ src, const int* __restrict__ dst, int E) {
    int i = (blockIdx.x * blockDim.x + threadIdx.x) * 4;
    if (i + 3 < E) {
        int4 s = *(const int4*)&src[i];
        int4 d = *(const int4*)&dst[i];
        int4 r = *(const int4*)&g_rank[i];
        float f0 = g_dis[s.x], f1 = g_dis[s.y], f2 = g_dis[s.z], f3 = g_dis[s.w];
        int p0 = g_rowoff[d.x] + r.x;
        int p1 = g_rowoff[d.y] + r.y;
        int p2 = g_rowoff[d.z] + r.z;
        int p3 = g_rowoff[d.w] + r.w;
        g_csr2[p0] = make_int2(s.x, __float_as_int(f0));
        g_csr2[p1] = make_int2(s.y, __float_as_int(f1));
        g_csr2[p2] = make_int2(s.z, __float_as_int(f2));
        g_csr2[p3] = make_int2(s.w, __float_as_int(f3));
    } else {
        for (int j = i; j < E; j++) {
            int sj = src[j];
            int p = g_rowoff[dst[j]] + g_rank[j];
            g_csr2[p] = make_int2(sj, __float_as_int(g_dis[sj]));
        }
    }
}

// ================= fp16 2-pass split GEMM (persistent) ==================
// C[nrows,128] = A[nrows,128] @ W[128,128]:  D = Ahi*W16 + Alo*W16
// A split fp16 hi/lo (error ~2^-22), W rounded to fp16 once (error ~2^-12).
// PERSISTENT: 148 blocks x 512 threads; W staged ONCE per block, then each
// block loops over row-tiles (128 rows each). 16 warps: warp = rowgrp*2 +
// colhalf, each 16 rows x 64 cols (32 acc regs).
#define WROW 72

__device__ __forceinline__ uint32_t pack_h2(__half a, __half b) {
    __half2 h = __halves2half2(a, b);
    return *(uint32_t*)&h;
}
__device__ __forceinline__ void split2h(float x, float y, uint32_t& hi, uint32_t& lo) {
    __half h0 = __float2half_rn(x), h1 = __float2half_rn(y);
    __half l0 = __float2half_rn(x - __half2float(h0));
    __half l1 = __float2half_rn(y - __half2float(h1));
    hi = pack_h2(h0, h1);
    lo = pack_h2(l0, l1);
}
__device__ __forceinline__ void mma_f16(float* c, const uint32_t* a, uint32_t b0, uint32_t b1) {
    asm volatile(
        "mma.sync.aligned.m16n8k16.row.col.f32.f16.f16.f32 "
        "{%0,%1,%2,%3}, {%4,%5,%6,%7}, {%8,%9}, {%0,%1,%2,%3};"
        : "+f"(c[0]), "+f"(c[1]), "+f"(c[2]), "+f"(c[3])
        : "r"(a[0]), "r"(a[1]), "r"(a[2]), "r"(a[3]), "r"(b0), "r"(b1));
}

__global__ __launch_bounds__(512) void k_gemm_mma(const float* __restrict__ A,
                                                  const float* __restrict__ W,
                                                  __half* __restrict__ C,
                                                  int nrows, int ntiles) {
    __shared__ uint32_t Wh[128 * WROW];

    int tid = threadIdx.x, wid = tid >> 5, lane = tid & 31;
    int g = lane >> 2, t = lane & 3;
    int rowgrp = wid >> 1, colhalf = wid & 1;

    // stage W as fp16 pairs, fragment-major — ONCE per block
    for (int idx = tid; idx < 64 * 128; idx += 512) {
        int p = idx >> 7, n = idx & 127;
        int k = p * 2;
        float w0 = W[k * FEAT + n];
        float w1 = W[(k + 1) * FEAT + n];
        int kstep = p >> 3, q = p & 7;
        int word = n * WROW + kstep * 8 + (q & 3) * 2 + (q >> 2);
        Wh[word] = pack_h2(__float2half_rn(w0), __float2half_rn(w1));
    }
    __syncthreads();

    const int bbase = colhalf * 8 * 8 * WROW + g * WROW;   // n0 = colhalf*8 + j

    for (int tile = blockIdx.x; tile < ntiles; tile += gridDim.x) {
        int r0 = tile * 128 + rowgrp * 16 + g;
        int r1 = r0 + 8;
        bool v0 = r0 < nrows, v1 = r1 < nrows;

        float acc[8][4];
        #pragma unroll
        for (int j = 0; j < 8; j++)
            #pragma unroll
            for (int c = 0; c < 4; c++) acc[j][c] = 0.0f;

        #pragma unroll
        for (int kstep = 0; kstep < 8; kstep++) {
            int ka = kstep * 16 + 2 * t;
            float2 z = make_float2(0.f, 0.f);
            float2 p00 = v0 ? *(const float2*)&A[r0 * FEAT + ka]     : z;
            float2 p01 = v0 ? *(const float2*)&A[r0 * FEAT + ka + 8] : z;
            float2 p10 = v1 ? *(const float2*)&A[r1 * FEAT + ka]     : z;
            float2 p11 = v1 ? *(const float2*)&A[r1 * FEAT + ka + 8] : z;
            uint32_t ahi[4], alo[4];
            split2h(p00.x, p00.y, ahi[0], alo[0]);
            split2h(p10.x, p10.y, ahi[1], alo[1]);
            split2h(p01.x, p01.y, ahi[2], alo[2]);
            split2h(p11.x, p11.y, ahi[3], alo[3]);

            int bk = kstep * 8 + t * 2;
            #pragma unroll
            for (int j = 0; j < 8; j++) {
                uint2 bh = *(const uint2*)&Wh[bbase + j * 8 * WROW + bk];
                mma_f16(acc[j], ahi, bh.x, bh.y);
                mma_f16(acc[j], alo, bh.x, bh.y);
            }
        }

        #pragma unroll
        for (int j = 0; j < 8; j++) {
            int col = (colhalf * 8 + j) * 8 + 2 * t;
            if (v0) *(__half2*)&C[r0 * FEAT + col] = __floats2half2_rn(acc[j][0], acc[j][1]);
            if (v1) *(__half2*)&C[r1 * FEAT + col] = __floats2half2_rn(acc[j][2], acc[j][3]);
        }
    }
}

// ================= aggregation (one warp per dst node, packed CSR) =======
__device__ __forceinline__ float elu1(float v) { return v > 0.0f ? v : expm1f(v); }

__device__ __forceinline__ float4 ld_row_h(const __half* __restrict__ T, int s, int lane) {
    uint2 u = *(const uint2*)(T + s * FEAT + lane * 4);
    __half2 h0 = *(__half2*)&u.x;
    __half2 h1 = *(__half2*)&u.y;
    float2 f0 = __half22float2(h0);
    float2 f1 = __half22float2(h1);
    return make_float4(f0.x, f0.y, f1.x, f1.y);
}

// FUSE_FINAL=0: Hout = ELU(acc+bias). FUSE_FINAL=1: out = ELU(acc+bias)@Wl + bl.
template<int FUSE_FINAL>
__global__ __launch_bounds__(256) void k_agg_t(const __half* __restrict__ T,
                                               const float* __restrict__ bias,
                                               float* __restrict__ Hout,
                                               const float* __restrict__ Wl,
                                               const float* __restrict__ bl,
                                               float* __restrict__ out) {
    int warp = (int)((blockIdx.x * blockDim.x + threadIdx.x) >> 5);
    int lane = threadIdx.x & 31;
    if (warp >= N_NODES) return;
    int node = warp;
    float dd = g_dis[node];

    float4 acc = ld_row_h(T, node, lane);
    float ws = dd * dd;                        // self-loop weight
    acc.x *= ws; acc.y *= ws; acc.z *= ws; acc.w *= ws;

    int beg = g_rowoff[node];
    int end = g_rowoff[node + 1];
    int e = beg;
    for (; e + 3 < end; e += 4) {
        int2 p0 = g_csr2[e],     p1 = g_csr2[e + 1];
        int2 p2 = g_csr2[e + 2], p3 = g_csr2[e + 3];
        float w0 = __int_as_float(p0.y) * dd, w1 = __int_as_float(p1.y) * dd;
        float w2 = __int_as_float(p2.y) * dd, w3 = __int_as_float(p3.y) * dd;
        float4 v0 = ld_row_h(T, p0.x, lane);
        float4 v1 = ld_row_h(T, p1.x, lane);
        float4 v2 = ld_row_h(T, p2.x, lane);
        float4 v3 = ld_row_h(T, p3.x, lane);
        acc.x = fmaf(w0, v0.x, fmaf(w1, v1.x, fmaf(w2, v2.x, fmaf(w3, v3.x, acc.x))));
        acc.y = fmaf(w0, v0.y, fmaf(w1, v1.y, fmaf(w2, v2.y, fmaf(w3, v3.y, acc.y))));
        acc.z = fmaf(w0, v0.z, fmaf(w1, v1.z, fmaf(w2, v2.z, fmaf(w3, v3.z, acc.z))));
        acc.w = fmaf(w0, v0.w, fmaf(w1, v1.w, fmaf(w2, v2.w, fmaf(w3, v3.w, acc.w))));
    }
    for (; e < end; e++) {
        int2 p0 = g_csr2[e];
        float w0 = __int_as_float(p0.y) * dd;
        float4 v0 = ld_row_h(T, p0.x, lane);
        acc.x = fmaf(w0, v0.x, acc.x);
        acc.y = fmaf(w0, v0.y, acc.y);
        acc.z = fmaf(w0, v0.z, acc.z);
        acc.w = fmaf(w0, v0.w, acc.w);
    }

    float4 b = *(const float4*)&bias[lane * 4];
    float4 r;
    r.x = elu1(acc.x + b.x);
    r.y = elu1(acc.y + b.y);
    r.z = elu1(acc.z + b.z);
    r.w = elu1(acc.w + b.w);

    if (FUSE_FINAL) {
        float4 w = *(const float4*)&Wl[lane * 4];
        float s = r.x * w.x + r.y * w.y + r.z * w.z + r.w * w.w;
        #pragma unroll
        for (int d = 16; d; d >>= 1) s += __shfl_xor_sync(0xffffffffu, s, d);
        if (lane == 0) out[node] = s + bl[0];
    } else {
        *(float4*)&Hout[node * FEAT + lane * 4] = r;
    }
}

// ================= launch =================
extern "C" void kernel_launch(void* const* d_in, const int* in_sizes, int n_in,
                              void* d_out, int out_size) {
    const float* x  = (const float*)d_in[0];
    const float* Ws = (const float*)d_in[1];
    const float* bs = (const float*)d_in[2];
    const float* Wl = (const float*)d_in[3];
    const float* bl = (const float*)d_in[4];
    const int*   ei = (const int*)d_in[5];
    const int E = in_sizes[5] / 2;
    const int* src = ei;
    const int* dst = ei + E;
    float* out = (float*)d_out;

    float* hbuf = nullptr;
    __half* tbuf = nullptr;
    void *degp = nullptr, *tsp = nullptr;
    cudaGetSymbolAddress((void**)&hbuf, g_bufH);
    cudaGetSymbolAddress((void**)&tbuf, g_bufT);
    cudaGetSymbolAddress(&degp, g_deg);
    cudaGetSymbolAddress(&tsp, g_tilestate);

    // graph structure
    cudaMemsetAsync(degp, 0, N_NODES * sizeof(int), 0);
    cudaMemsetAsync(tsp, 0, SCAN_NT * sizeof(unsigned long long), 0);
    k_count<<<(E / 4 + 255) / 256, 256>>>(dst, E);
    k_scan_dl<<<SCAN_NT, 1024>>>();
    k_fill<<<(E / 4 + 255) / 256, 256>>>(src, dst, E);

    const int ntiles = (N_NODES + 127) / 128;   // 391
    const int nagg   = (N_NODES + 7) / 8;
    for (int i = 0; i < 3; i++) {
        const float* Ain = (i == 0) ? x : hbuf;
        k_gemm_mma<<<148, 512>>>(Ain, Ws + i * FEAT * FEAT, tbuf, N_NODES, ntiles);
        if (i < 2)
            k_agg_t<0><<<nagg, 256>>>(tbuf, bs + i * FEAT, hbuf, nullptr, nullptr, nullptr);
        else
            k_agg_t<1><<<nagg, 256>>>(tbuf, bs + i * FEAT, nullptr, Wl, bl, out);
    }
}

// round 11
// speedup vs baseline: 1.1061x; 1.0693x over previous
#include <cuda_runtime.h>
#include <cuda_fp16.h>
#include <math.h>
#include <stdint.h>

#define N_NODES 50000
#define FEAT    128
#define MAX_E   800000
#define SCAN_TILE 4096
#define SCAN_NT ((N_NODES + SCAN_TILE - 1) / SCAN_TILE)   // 13

// ---- scratch (static __device__ arrays; no runtime allocation) ----
__device__ __half g_bufT[N_NODES * FEAT];   // post-GEMM features (fp16)
__device__ __half g_bufH[N_NODES * FEAT];   // post-aggregation features (fp16)
__device__ int   g_deg[N_NODES];
__device__ float g_dis[N_NODES];
__device__ int   g_rowoff[N_NODES + 1];
__device__ int   g_rank[MAX_E];             // per-edge rank within its dst list
__device__ int2  g_csr2[MAX_E];             // (src, dis[src]) per edge
__device__ unsigned long long g_tilestate[SCAN_NT];

// ================= CSR construction =================
// pass 1: count in-degree AND record each edge's rank within its dst bucket
__global__ void k_count(const int* __restrict__ dst, int E) {
    int i = (blockIdx.x * blockDim.x + threadIdx.x) * 4;
    if (i + 3 < E) {
        int4 d = *(const int4*)&dst[i];
        int4 r;
        r.x = atomicAdd(&g_deg[d.x], 1);
        r.y = atomicAdd(&g_deg[d.y], 1);
        r.z = atomicAdd(&g_deg[d.z], 1);
        r.w = atomicAdd(&g_deg[d.w], 1);
        *(int4*)&g_rank[i] = r;
    } else {
        for (int j = i; j < E; j++) g_rank[j] = atomicAdd(&g_deg[dst[j]], 1);
    }
}

// decoupled-lookback scan: rowoff = exclusive scan of deg; also dis = rsqrt(deg+1)
__global__ __launch_bounds__(1024) void k_scan_dl() {
    __shared__ int sh_w[32];
    __shared__ unsigned int sh_prefix;
    int tid = threadIdx.x, lane = tid & 31, wid = tid >> 5;
    int tile = blockIdx.x;
    int i0 = tile * SCAN_TILE + tid * 4;

    int4 v = make_int4(0, 0, 0, 0);
    if (i0 < N_NODES) {
        v = *(const int4*)&g_deg[i0];
        float4 d;
        d.x = rsqrtf((float)(v.x + 1));
        d.y = rsqrtf((float)(v.y + 1));
        d.z = rsqrtf((float)(v.z + 1));
        d.w = rsqrtf((float)(v.w + 1));
        *(float4*)&g_dis[i0] = d;
    }
    int t0 = v.x, t1 = t0 + v.y, t2 = t1 + v.z, t3 = t2 + v.w;
    int sc = t3;
    #pragma unroll
    for (int d = 1; d < 32; d <<= 1) {
        int t = __shfl_up_sync(0xffffffffu, sc, d);
        if (lane >= d) sc += t;
    }
    if (lane == 31) sh_w[wid] = sc;
    __syncthreads();
    if (wid == 0) {
        int ws = sh_w[lane];
        #pragma unroll
        for (int d = 1; d < 32; d <<= 1) {
            int t = __shfl_up_sync(0xffffffffu, ws, d);
            if (lane >= d) ws += t;
        }
        sh_w[lane] = ws;
    }
    __syncthreads();
    int total = sh_w[31];
    int thr_excl = (wid ? sh_w[wid - 1] : 0) + sc - t3;

    if (tid == 0) {
        unsigned long long st = ((tile == 0) ? (2ULL << 32) : (1ULL << 32)) | (unsigned)total;
        atomicExch(&g_tilestate[tile], st);
    }
    if (wid == 0) {
        unsigned int prefix = 0;
        if (tile > 0) {
            bool have = lane < tile;
            unsigned long long s = 0;
            if (have) {
                do { s = *(volatile unsigned long long*)&g_tilestate[tile - 1 - lane]; }
                while ((unsigned)(s >> 32) == 0u);
            }
            unsigned flag = (unsigned)(s >> 32);
            unsigned mask = __ballot_sync(0xffffffffu, have && flag == 2u);
            int firstInc = __ffs(mask) - 1;   // exists: tile 0 is always INCLUSIVE
            unsigned contrib = (have && lane <= firstInc) ? (unsigned)s : 0u;
            #pragma unroll
            for (int d = 16; d; d >>= 1) contrib += __shfl_xor_sync(0xffffffffu, contrib, d);
            prefix = contrib;
            if (lane == 0)
                atomicExch(&g_tilestate[tile], (2ULL << 32) | (unsigned)(prefix + (unsigned)total));
        }
        if (lane == 0) sh_prefix = prefix;
    }
    __syncthreads();
    int base = (int)sh_prefix + thr_excl;
    if (i0 < N_NODES) {
        int4 o = make_int4(base, base + t0, base + t1, base + t2);
        *(int4*)&g_rowoff[i0] = o;
    }
    if (tile == SCAN_NT - 1 && tid == 0) g_rowoff[N_NODES] = (int)sh_prefix + total;
}

// pass 2 (no atomics): scatter (src, dis[src]) to rowoff[dst] + rank
__global__ void k_fill(const int* __restrict__ src, const int* __restrict__ dst, int E) {
    int i = (blockIdx.x * blockDim.x + threadIdx.x) * 4;
    if (i + 3 < E) {
        int4 s = *(const int4*)&src[i];
        int4 d = *(const int4*)&dst[i];
        int4 r = *(const int4*)&g_rank[i];
        float f0 = g_dis[s.x], f1 = g_dis[s.y], f2 = g_dis[s.z], f3 = g_dis[s.w];
        int p0 = g_rowoff[d.x] + r.x;
        int p1 = g_rowoff[d.y] + r.y;
        int p2 = g_rowoff[d.z] + r.z;
        int p3 = g_rowoff[d.w] + r.w;
        g_csr2[p0] = make_int2(s.x, __float_as_int(f0));
        g_csr2[p1] = make_int2(s.y, __float_as_int(f1));
        g_csr2[p2] = make_int2(s.z, __float_as_int(f2));
        g_csr2[p3] = make_int2(s.w, __float_as_int(f3));
    } else {
        for (int j = i; j < E; j++) {
            int sj = src[j];
            int p = g_rowoff[dst[j]] + g_rank[j];
            g_csr2[p] = make_int2(sj, __float_as_int(g_dis[sj]));
        }
    }
}

// ================= GEMM common =================
// W staged fragment-major fp16 in smem; 256 threads / 8 warps / block;
// tile = 128 rows x 128 cols; each warp 16 rows x 128 cols.
#define WROW 72

__device__ __forceinline__ uint32_t pack_h2(__half a, __half b) {
    __half2 h = __halves2half2(a, b);
    return *(uint32_t*)&h;
}
__device__ __forceinline__ void split2h(float x, float y, uint32_t& hi, uint32_t& lo) {
    __half h0 = __float2half_rn(x), h1 = __float2half_rn(y);
    __half l0 = __float2half_rn(x - __half2float(h0));
    __half l1 = __float2half_rn(y - __half2float(h1));
    hi = pack_h2(h0, h1);
    lo = pack_h2(l0, l1);
}
__device__ __forceinline__ void mma_f16(float* c, const uint32_t* a, uint32_t b0, uint32_t b1) {
    asm volatile(
        "mma.sync.aligned.m16n8k16.row.col.f32.f16.f16.f32 "
        "{%0,%1,%2,%3}, {%4,%5,%6,%7}, {%8,%9}, {%0,%1,%2,%3};"
        : "+f"(c[0]), "+f"(c[1]), "+f"(c[2]), "+f"(c[3])
        : "r"(a[0]), "r"(a[1]), "r"(a[2]), "r"(a[3]), "r"(b0), "r"(b1));
}
__device__ __forceinline__ void stage_W(uint32_t* Wh, const float* __restrict__ W, int tid) {
    for (int idx = tid; idx < 64 * 128; idx += 256) {
        int p = idx >> 7, n = idx & 127;
        int k = p * 2;
        float w0 = W[k * FEAT + n];
        float w1 = W[(k + 1) * FEAT + n];
        int kstep = p >> 3, q = p & 7;
        int word = n * WROW + kstep * 8 + (q & 3) * 2 + (q >> 2);
        Wh[word] = pack_h2(__float2half_rn(w0), __float2half_rn(w1));
    }
}

// --- layer 1: fp32 A, 2-pass hi/lo split (round-7 proven config) ---
__global__ __launch_bounds__(256) void k_gemm_split(const float* __restrict__ A,
                                                    const float* __restrict__ W,
                                                    __half* __restrict__ C, int nrows) {
    __shared__ uint32_t Wh[128 * WROW];
    int tid = threadIdx.x, wid = tid >> 5, lane = tid & 31;
    int g = lane >> 2, t = lane & 3;
    stage_W(Wh, W, tid);
    __syncthreads();

    int r0 = blockIdx.x * 128 + wid * 16 + g;
    int r1 = r0 + 8;
    bool v0 = r0 < nrows, v1 = r1 < nrows;

    float acc[16][4];
    #pragma unroll
    for (int n0 = 0; n0 < 16; n0++)
        #pragma unroll
        for (int j = 0; j < 4; j++) acc[n0][j] = 0.0f;

    #pragma unroll
    for (int kstep = 0; kstep < 8; kstep++) {
        int ka = kstep * 16 + 2 * t;
        float2 z = make_float2(0.f, 0.f);
        float2 p00 = v0 ? *(const float2*)&A[r0 * FEAT + ka]     : z;
        float2 p01 = v0 ? *(const float2*)&A[r0 * FEAT + ka + 8] : z;
        float2 p10 = v1 ? *(const float2*)&A[r1 * FEAT + ka]     : z;
        float2 p11 = v1 ? *(const float2*)&A[r1 * FEAT + ka + 8] : z;
        uint32_t ahi[4], alo[4];
        split2h(p00.x, p00.y, ahi[0], alo[0]);
        split2h(p10.x, p10.y, ahi[1], alo[1]);
        split2h(p01.x, p01.y, ahi[2], alo[2]);
        split2h(p11.x, p11.y, ahi[3], alo[3]);

        int bword = g * WROW + kstep * 8 + t * 2;
        #pragma unroll
        for (int n0 = 0; n0 < 16; n0++) {
            uint2 bh = *(const uint2*)&Wh[n0 * 8 * WROW + bword];
            mma_f16(acc[n0], ahi, bh.x, bh.y);
            mma_f16(acc[n0], alo, bh.x, bh.y);
        }
    }

    #pragma unroll
    for (int n0 = 0; n0 < 16; n0++) {
        int col = n0 * 8 + 2 * t;
        if (v0) *(__half2*)&C[r0 * FEAT + col] = __floats2half2_rn(acc[n0][0], acc[n0][1]);
        if (v1) *(__half2*)&C[r1 * FEAT + col] = __floats2half2_rn(acc[n0][2], acc[n0][3]);
    }
}

// --- layers 2,3: fp16 A, single pass, no conversion math ---
__global__ __launch_bounds__(256) void k_gemm_h(const __half* __restrict__ A,
                                                const float* __restrict__ W,
                                                __half* __restrict__ C, int nrows) {
    __shared__ uint32_t Wh[128 * WROW];
    int tid = threadIdx.x, wid = tid >> 5, lane = tid & 31;
    int g = lane >> 2, t = lane & 3;
    stage_W(Wh, W, tid);
    __syncthreads();

    int r0 = blockIdx.x * 128 + wid * 16 + g;
    int r1 = r0 + 8;
    bool v0 = r0 < nrows, v1 = r1 < nrows;

    float acc[16][4];
    #pragma unroll
    for (int n0 = 0; n0 < 16; n0++)
        #pragma unroll
        for (int j = 0; j < 4; j++) acc[n0][j] = 0.0f;

    #pragma unroll
    for (int kstep = 0; kstep < 8; kstep++) {
        int ka = kstep * 16 + 2 * t;
        uint32_t a[4];
        a[0] = v0 ? *(const uint32_t*)&A[r0 * FEAT + ka]     : 0u;
        a[1] = v1 ? *(const uint32_t*)&A[r1 * FEAT + ka]     : 0u;
        a[2] = v0 ? *(const uint32_t*)&A[r0 * FEAT + ka + 8] : 0u;
        a[3] = v1 ? *(const uint32_t*)&A[r1 * FEAT + ka + 8] : 0u;

        int bword = g * WROW + kstep * 8 + t * 2;
        #pragma unroll
        for (int n0 = 0; n0 < 16; n0++) {
            uint2 bh = *(const uint2*)&Wh[n0 * 8 * WROW + bword];
            mma_f16(acc[n0], a, bh.x, bh.y);
        }
    }

    #pragma unroll
    for (int n0 = 0; n0 < 16; n0++) {
        int col = n0 * 8 + 2 * t;
        if (v0) *(__half2*)&C[r0 * FEAT + col] = __floats2half2_rn(acc[n0][0], acc[n0][1]);
        if (v1) *(__half2*)&C[r1 * FEAT + col] = __floats2half2_rn(acc[n0][2], acc[n0][3]);
    }
}

// ================= aggregation (one warp per dst node, packed CSR) =======
__device__ __forceinline__ float elu1(float v) { return v > 0.0f ? v : expm1f(v); }

__device__ __forceinline__ float4 ld_row_h(const __half* __restrict__ T, int s, int lane) {
    uint2 u = *(const uint2*)(T + s * FEAT + lane * 4);
    __half2 h0 = *(__half2*)&u.x;
    __half2 h1 = *(__half2*)&u.y;
    float2 f0 = __half22float2(h0);
    float2 f1 = __half22float2(h1);
    return make_float4(f0.x, f0.y, f1.x, f1.y);
}

// FUSE_FINAL=0: Hout = fp16(ELU(acc+bias)). FUSE_FINAL=1: out = ELU(acc+bias)@Wl + bl.
template<int FUSE_FINAL>
__global__ __launch_bounds__(256) void k_agg_t(const __half* __restrict__ T,
                                               const float* __restrict__ bias,
                                               __half* __restrict__ Hout,
                                               const float* __restrict__ Wl,
                                               const float* __restrict__ bl,
                                               float* __restrict__ out) {
    int warp = (int)((blockIdx.x * blockDim.x + threadIdx.x) >> 5);
    int lane = threadIdx.x & 31;
    if (warp >= N_NODES) return;
    int node = warp;
    float dd = g_dis[node];

    float4 acc = ld_row_h(T, node, lane);
    float ws = dd * dd;                        // self-loop weight
    acc.x *= ws; acc.y *= ws; acc.z *= ws; acc.w *= ws;

    int beg = g_rowoff[node];
    int end = g_rowoff[node + 1];
    int e = beg;
    for (; e + 3 < end; e += 4) {
        int2 p0 = g_csr2[e],     p1 = g_csr2[e + 1];
        int2 p2 = g_csr2[e + 2], p3 = g_csr2[e + 3];
        float w0 = __int_as_float(p0.y) * dd, w1 = __int_as_float(p1.y) * dd;
        float w2 = __int_as_float(p2.y) * dd, w3 = __int_as_float(p3.y) * dd;
        float4 v0 = ld_row_h(T, p0.x, lane);
        float4 v1 = ld_row_h(T, p1.x, lane);
        float4 v2 = ld_row_h(T, p2.x, lane);
        float4 v3 = ld_row_h(T, p3.x, lane);
        acc.x = fmaf(w0, v0.x, fmaf(w1, v1.x, fmaf(w2, v2.x, fmaf(w3, v3.x, acc.x))));
        acc.y = fmaf(w0, v0.y, fmaf(w1, v1.y, fmaf(w2, v2.y, fmaf(w3, v3.y, acc.y))));
        acc.z = fmaf(w0, v0.z, fmaf(w1, v1.z, fmaf(w2, v2.z, fmaf(w3, v3.z, acc.z))));
        acc.w = fmaf(w0, v0.w, fmaf(w1, v1.w, fmaf(w2, v2.w, fmaf(w3, v3.w, acc.w))));
    }
    for (; e < end; e++) {
        int2 p0 = g_csr2[e];
        float w0 = __int_as_float(p0.y) * dd;
        float4 v0 = ld_row_h(T, p0.x, lane);
        acc.x = fmaf(w0, v0.x, acc.x);
        acc.y = fmaf(w0, v0.y, acc.y);
        acc.z = fmaf(w0, v0.z, acc.z);
        acc.w = fmaf(w0, v0.w, acc.w);
    }

    float4 b = *(const float4*)&bias[lane * 4];
    float4 r;
    r.x = elu1(acc.x + b.x);
    r.y = elu1(acc.y + b.y);
    r.z = elu1(acc.z + b.z);
    r.w = elu1(acc.w + b.w);

    if (FUSE_FINAL) {
        float4 w = *(const float4*)&Wl[lane * 4];
        float s = r.x * w.x + r.y * w.y + r.z * w.z + r.w * w.w;
        #pragma unroll
        for (int d = 16; d; d >>= 1) s += __shfl_xor_sync(0xffffffffu, s, d);
        if (lane == 0) out[node] = s + bl[0];
    } else {
        uint2 st;
        __half2 h0 = __floats2half2_rn(r.x, r.y);
        __half2 h1 = __floats2half2_rn(r.z, r.w);
        st.x = *(uint32_t*)&h0;
        st.y = *(uint32_t*)&h1;
        *(uint2*)&Hout[node * FEAT + lane * 4] = st;
    }
}

// ================= launch =================
extern "C" void kernel_launch(void* const* d_in, const int* in_sizes, int n_in,
                              void* d_out, int out_size) {
    const float* x  = (const float*)d_in[0];
    const float* Ws = (const float*)d_in[1];
    const float* bs = (const float*)d_in[2];
    const float* Wl = (const float*)d_in[3];
    const float* bl = (const float*)d_in[4];
    const int*   ei = (const int*)d_in[5];
    const int E = in_sizes[5] / 2;
    const int* src = ei;
    const int* dst = ei + E;
    float* out = (float*)d_out;

    __half* hbuf = nullptr;
    __half* tbuf = nullptr;
    void *degp = nullptr, *tsp = nullptr;
    cudaGetSymbolAddress((void**)&hbuf, g_bufH);
    cudaGetSymbolAddress((void**)&tbuf, g_bufT);
    cudaGetSymbolAddress(&degp, g_deg);
    cudaGetSymbolAddress(&tsp, g_tilestate);

    // graph structure
    cudaMemsetAsync(degp, 0, N_NODES * sizeof(int), 0);
    cudaMemsetAsync(tsp, 0, SCAN_NT * sizeof(unsigned long long), 0);
    k_count<<<(E / 4 + 255) / 256, 256>>>(dst, E);
    k_scan_dl<<<SCAN_NT, 1024>>>();
    k_fill<<<(E / 4 + 255) / 256, 256>>>(src, dst, E);

    const int ntiles = (N_NODES + 127) / 128;   // 391
    const int nagg   = (N_NODES + 7) / 8;

    // layer 1: fp32 input, split GEMM
    k_gemm_split<<<ntiles, 256>>>(x, Ws, tbuf, N_NODES);
    k_agg_t<0><<<nagg, 256>>>(tbuf, bs, hbuf, nullptr, nullptr, nullptr);
    // layer 2: fp16 input, single-pass GEMM
    k_gemm_h<<<ntiles, 256>>>(hbuf, Ws + FEAT * FEAT, tbuf, N_NODES);
    k_agg_t<0><<<nagg, 256>>>(tbuf, bs + FEAT, hbuf, nullptr, nullptr, nullptr);
    // layer 3: fp16 input, fused final projection
    k_gemm_h<<<ntiles, 256>>>(hbuf, Ws + 2 * FEAT * FEAT, tbuf, N_NODES);
    k_agg_t<1><<<nagg, 256>>>(tbuf, bs + 2 * FEAT, nullptr, Wl, bl, out);
}